// round 7
// baseline (speedup 1.0000x reference)
#include <cuda_runtime.h>
#include <cuda_fp16.h>
#include <stdint.h>
#include <math.h>

#define NB 128
#define NI 1152
#define IC 16                   // i per k_hat CTA
#define ICHUNKS (NI/IC)         // 72
#define BC 16                   // b per k_hat CTA
#define SPLIT 6                 // i-splits in routing passes
#define IPS (NI/SPLIT)          // 192
#define PSTEPS (IPS/16)         // 12 (16 i per CTA-step)

// Scratch (static device globals; no runtime allocation)
__device__ __half   g_hat[(size_t)NB * NI * 256];  // [b][i][n*16+e], 75.5 MB
__device__ float    g_s0p[(size_t)ICHUNKS * NB * 256];
__device__ float    g_sp1[SPLIT * NB * 256];
__device__ float    g_sp2[SPLIT * NB * 256];
__device__ float    g_vec0[NB * 256];              // out0
__device__ unsigned g_tick[NB];                    // zero-init; reset by finalizer

// ---- packed f32x2 helpers (Blackwell FFMA2 via PTX) ----
__device__ __forceinline__ uint64_t pk(float a, float b) {
    uint64_t r; asm("mov.b64 %0, {%1,%2};" : "=l"(r) : "f"(a), "f"(b)); return r;
}
__device__ __forceinline__ void unpk(uint64_t v, float& lo, float& hi) {
    asm("mov.b64 {%0,%1}, %2;" : "=f"(lo), "=f"(hi) : "l"(v));
}
__device__ __forceinline__ uint64_t mul2(uint64_t a, uint64_t b) {
    uint64_t r; asm("mul.rn.f32x2 %0, %1, %2;" : "=l"(r) : "l"(a), "l"(b)); return r;
}
__device__ __forceinline__ void fma2(uint64_t& d, uint64_t a, uint64_t b) {
    asm("fma.rn.f32x2 %0, %1, %2, %3;" : "=l"(d) : "l"(a), "l"(b), "l"(d));
}
__device__ __forceinline__ void add2(uint64_t& d, uint64_t a) {
    asm("add.rn.f32x2 %0, %1, %2;" : "=l"(d) : "l"(a), "l"(d));
}

// ---------------------------------------------------------------------------
// k_hat: hat[b,i,n,e] = sum_d x[b,i,d]*W[n,i,e,d], fp16 out, e-pair packed.
// grid (72 i-chunks of 16, 8 b-blocks of 16)  [576 CTAs: W L2 traffic = 75MB]
// 256 threads: t = islot*128 + n*8 + ep  (2 interleaved i's, 8 e-pairs).
// One STG.32 (half2) per (b,i) per thread. Iter-0 partials combined across
// islot in smem (reusing the x-tile buffer) -> 72 chunks.
// ---------------------------------------------------------------------------
__global__ void __launch_bounds__(256) k_hat(const float* __restrict__ x,
                                             const float* __restrict__ W) {
    __shared__ uint64_t sbuf[BC * IC * 8];   // 16KB: x splat, then combine buf
    uint64_t (*sxs)[IC][8] = reinterpret_cast<uint64_t (*)[IC][8]>(sbuf);

    const int t  = threadIdx.x;
    const int i0 = blockIdx.x * IC;
    const int b0 = blockIdx.y * BC;

    for (int k = 0; k < 8; ++k) {
        int idx = t + k * 256;
        int bb = idx >> 7, rem = idx & 127;
        int ii = rem >> 3, d = rem & 7;
        float v = x[((size_t)(b0 + bb) * NI + i0 + ii) * 8 + d];
        sxs[bb][ii][d] = pk(v, v);
    }
    __syncthreads();

    const int islot = t >> 7, r = t & 127;
    const int n = r >> 3, ep = r & 7;
    const float4* wp = reinterpret_cast<const float4*>(W)
                     + ((size_t)(n * NI + i0 + islot) * 16 + 2 * ep) * 2;

    uint64_t s0[BC];
#pragma unroll
    for (int k = 0; k < BC; ++k) s0[k] = 0ull;

    for (int i = islot; i < IC; i += 2) {
        float4 wa0 = wp[0], wa1 = wp[1];   // e = 2ep,   d 0..7
        float4 wb0 = wp[2], wb1 = wp[3];   // e = 2ep+1, d 0..7
        wp += 64;                          // advance 2 i

        uint64_t pw[8];
        pw[0] = pk(wa0.x, wb0.x); pw[1] = pk(wa0.y, wb0.y);
        pw[2] = pk(wa0.z, wb0.z); pw[3] = pk(wa0.w, wb0.w);
        pw[4] = pk(wa1.x, wb1.x); pw[5] = pk(wa1.y, wb1.y);
        pw[6] = pk(wa1.z, wb1.z); pw[7] = pk(wa1.w, wb1.w);

#pragma unroll
        for (int bb = 0; bb < BC; ++bb) {
            const uint64_t* xp = &sxs[bb][i][0];
            uint64_t acc = mul2(pw[0], xp[0]);
            fma2(acc, pw[1], xp[1]);
            fma2(acc, pw[2], xp[2]);
            fma2(acc, pw[3], xp[3]);
            fma2(acc, pw[4], xp[4]);
            fma2(acc, pw[5], xp[5]);
            fma2(acc, pw[6], xp[6]);
            fma2(acc, pw[7], xp[7]);
            add2(s0[bb], acc);
            float lo, hi; unpk(acc, lo, hi);
            __half2 h = __floats2half2_rn(lo, hi);
            *reinterpret_cast<__half2*>(
                &g_hat[((size_t)(b0 + bb) * NI + i0 + i) * 256 + n * 16 + 2 * ep]) = h;
        }
    }

    // Combine islot partials (reuse sbuf) -> one chunk per CTA
    __syncthreads();
    uint64_t* scmb = sbuf;   // [r][bb] layout: r*BC + bb
    if (islot == 1) {
#pragma unroll
        for (int bb = 0; bb < BC; ++bb) scmb[r * BC + bb] = s0[bb];
    }
    __syncthreads();
    if (islot == 0) {
#pragma unroll
        for (int bb = 0; bb < BC; ++bb) {
            float lo, hi, ol, oh;
            unpk(s0[bb], lo, hi);
            unpk(scmb[r * BC + bb], ol, oh);
            *reinterpret_cast<float2*>(
                &g_s0p[((size_t)blockIdx.x * NB + b0 + bb) * 256 + n * 16 + 2 * ep])
                = make_float2(lo + ol, hi + oh);
        }
    }
}

// squash along e via warp butterfly over low 4 lane bits (t = n*16+e)
__device__ __forceinline__ float squash_val(float sv) {
    float sq = sv * sv;
    sq += __shfl_xor_sync(0xffffffffu, sq, 1);
    sq += __shfl_xor_sync(0xffffffffu, sq, 2);
    sq += __shfl_xor_sync(0xffffffffu, sq, 4);
    sq += __shfl_xor_sync(0xffffffffu, sq, 8);
    float scale = sq / ((1.f + sq) * sqrtf(sq));
    return sv * scale;
}

// One i: fp16 hat fragment -> logit dot (packed), softmax over n (4 shfl),
// packed-fma accumulate into sacc.
__device__ __forceinline__ void step_i(uint4 A0, uint4 A1,
                                       const uint64_t vecp[8], uint64_t sacc[8]) {
    uint64_t fp[8];
    const __half2* ha = reinterpret_cast<const __half2*>(&A0);
#pragma unroll
    for (int j = 0; j < 4; ++j) { float2 v = __half22float2(ha[j]); fp[j] = pk(v.x, v.y); }
    const __half2* hb = reinterpret_cast<const __half2*>(&A1);
#pragma unroll
    for (int j = 0; j < 4; ++j) { float2 v = __half22float2(hb[j]); fp[4+j] = pk(v.x, v.y); }

    uint64_t dacc = mul2(vecp[0], fp[0]);
#pragma unroll
    for (int j = 1; j < 8; ++j) fma2(dacc, vecp[j], fp[j]);
    float dlo, dhi; unpk(dacc, dlo, dhi);
    float E = __expf(dlo + dhi);
    float den = E;
    den += __shfl_xor_sync(0xffffffffu, den, 1);
    den += __shfl_xor_sync(0xffffffffu, den, 2);
    den += __shfl_xor_sync(0xffffffffu, den, 4);
    den += __shfl_xor_sync(0xffffffffu, den, 8);
    float c = __fdividef(E, den);
    uint64_t cp = pk(c, c);
#pragma unroll
    for (int j = 0; j < 8; ++j) fma2(sacc[j], cp, fp[j]);
}

// ---------------------------------------------------------------------------
// k_pass: fused head (build vec) + one routing sweep. grid (128 b, 6 splits).
// stage 1: vec = out0 = squash(sum_i hat /16 + Bias)     [g_s0p]
// stage 2: vec = out0 + out1; last CTA per b finalizes output (no 4th kernel).
// ---------------------------------------------------------------------------
__global__ void __launch_bounds__(256) k_pass(const float* __restrict__ Bias,
                                              float* __restrict__ out, int stage) {
    __shared__ float sVec[256];
    __shared__ float sRed[16][256];
    __shared__ int   sLast;

    const int b = blockIdx.x, isp = blockIdx.y;
    const int t = threadIdx.x, warp = t >> 5, lane = t & 31;
    const int n = lane & 15, islot = lane >> 4;

    // --- head: build vec for this batch (redundant per CTA, cheap L2 hits) ---
    {
        float sv = 0.f;
        if (stage == 1) {
            for (int c = 0; c < ICHUNKS; ++c)
                sv += g_s0p[((size_t)c * NB + b) * 256 + t];
            sv = sv * (1.f / 16.f) + Bias[t];
            float o = squash_val(sv);
            sVec[t] = o;
            if (isp == 0) g_vec0[b * 256 + t] = o;
        } else {
#pragma unroll
            for (int c = 0; c < SPLIT; ++c)
                sv += g_sp1[((size_t)c * NB + b) * 256 + t];
            sv += Bias[t];
            sVec[t] = g_vec0[b * 256 + t] + squash_val(sv);
        }
    }
    __syncthreads();

    uint64_t vecp[8];
#pragma unroll
    for (int j = 0; j < 8; ++j)
        vecp[j] = pk(sVec[n * 16 + 2*j], sVec[n * 16 + 2*j + 1]);

    const int iStart = isp * IPS + warp * 2 + islot;
    const uint4* p = reinterpret_cast<const uint4*>(g_hat)
                   + ((size_t)b * NI + iStart) * 32 + n * 2;
    const int S = 16 * 32;   // 16 i per CTA-step, 32 uint4 per i

    uint64_t sacc[8];
#pragma unroll
    for (int j = 0; j < 8; ++j) sacc[j] = 0ull;

    // 2-step unroll, 4 LDG.128 in flight per lane
    uint4 A0 = p[0], A1 = p[1], B0 = p[S], B1 = p[S + 1];
    for (int s = 0; s < PSTEPS; s += 2) {
        uint4 C0, C1, D0, D1;
        if (s + 2 < PSTEPS) {
            C0 = p[2 * S]; C1 = p[2 * S + 1];
            D0 = p[3 * S]; D1 = p[3 * S + 1];
        }
        p += 2 * S;
        step_i(A0, A1, vecp, sacc);
        step_i(B0, B1, vecp, sacc);
        A0 = C0; A1 = C1; B0 = D0; B1 = D1;
    }

    const int slot = warp * 2 + islot;
#pragma unroll
    for (int j = 0; j < 8; ++j) {
        float lo, hi; unpk(sacc[j], lo, hi);
        sRed[slot][n * 16 + 2*j]     = lo;
        sRed[slot][n * 16 + 2*j + 1] = hi;
    }
    __syncthreads();

    float sv = 0.f;
#pragma unroll
    for (int w = 0; w < 16; ++w) sv += sRed[w][t];

    if (stage == 1) {
        g_sp1[((size_t)isp * NB + b) * 256 + t] = sv;
        return;
    }

    // stage 2: write partial, last CTA per b finalizes (no spin; safe)
    g_sp2[((size_t)isp * NB + b) * 256 + t] = sv;
    __threadfence();
    __syncthreads();
    if (t == 0) {
        unsigned old = atomicAdd(&g_tick[b], 1u);
        sLast = (old == SPLIT - 1);
    }
    __syncthreads();
    if (sLast) {
        __threadfence();
        float fv = 0.f;
#pragma unroll
        for (int c = 0; c < SPLIT; ++c)
            fv += g_sp2[((size_t)c * NB + b) * 256 + t];
        fv += Bias[t];
        out[b * 256 + t] = squash_val(fv);
        if (t == 0) g_tick[b] = 0;    // reset for graph-replay determinism
    }
}

extern "C" void kernel_launch(void* const* d_in, const int* in_sizes, int n_in,
                              void* d_out, int out_size) {
    const float* x    = (const float*)d_in[0];   // [128,1152,8]
    const float* W    = (const float*)d_in[1];   // [16,1152,16,8]
    const float* Bias = (const float*)d_in[2];   // [16,16]
    float* out = (float*)d_out;                  // [128,16,16]

    k_hat<<<dim3(ICHUNKS, NB / BC), 256>>>(x, W);     // 576 CTAs
    k_pass<<<dim3(NB, SPLIT), 256>>>(Bias, out, 1);   // pass 1
    k_pass<<<dim3(NB, SPLIT), 256>>>(Bias, out, 2);   // pass 2 + fused finalize
}

// round 8
// speedup vs baseline: 1.4365x; 1.4365x over previous
#include <cuda_runtime.h>
#include <cuda_fp16.h>
#include <stdint.h>
#include <math.h>

#define NB 128
#define NI 1152
#define IC 16                   // i per k_hat CTA
#define ICHUNKS (NI/IC)         // 72
#define SLOTS 48                // i-slots in k_route (24 warps x 2)
#define STEPS (NI/SLOTS)        // 24

// Scratch (static device globals; no runtime allocation)
__device__ __half g_hat[(size_t)NB * NI * 256];   // [b][i][n*16+e], 75.5 MB
__device__ float  g_s0p[(size_t)ICHUNKS * NB * 256];

// ---- packed f32x2 helpers (Blackwell FFMA2 via PTX) ----
__device__ __forceinline__ uint64_t pk(float a, float b) {
    uint64_t r; asm("mov.b64 %0, {%1,%2};" : "=l"(r) : "f"(a), "f"(b)); return r;
}
__device__ __forceinline__ void unpk(uint64_t v, float& lo, float& hi) {
    asm("mov.b64 {%0,%1}, %2;" : "=f"(lo), "=f"(hi) : "l"(v));
}
__device__ __forceinline__ uint64_t mul2(uint64_t a, uint64_t b) {
    uint64_t r; asm("mul.rn.f32x2 %0, %1, %2;" : "=l"(r) : "l"(a), "l"(b)); return r;
}
__device__ __forceinline__ void fma2(uint64_t& d, uint64_t a, uint64_t b) {
    asm("fma.rn.f32x2 %0, %1, %2, %3;" : "=l"(d) : "l"(a), "l"(b), "l"(d));
}
__device__ __forceinline__ void add2(uint64_t& d, uint64_t a) {
    asm("add.rn.f32x2 %0, %1, %2;" : "=l"(d) : "l"(a), "l"(d));
}

// ---------------------------------------------------------------------------
// k_hat (R4-proven structure): hat[b,i,n,e] = sum_d x[b,i,d]*W[n,i,e,d].
// grid (72 i-chunks of 16, 8 b-blocks of 16), 256 threads: t = n*16 + e.
// Batch pairs via packed f32x2 FMA; x pre-packed (x_b, x_b+1) in smem,
// read back with LDS.128 (ulonglong2). Emits iter-0 partials per chunk.
// ---------------------------------------------------------------------------
__global__ void __launch_bounds__(256) k_hat(const float* __restrict__ x,
                                             const float* __restrict__ W) {
    __shared__ uint64_t sxp[8][IC][8];   // [b-pair][i][d] = (x_b, x_b+1), 8KB
    const int t  = threadIdx.x;
    const int i0 = blockIdx.x * IC;
    const int b0 = blockIdx.y * 16;

    for (int idx = t; idx < 8 * IC * 8; idx += 256) {
        int b2 = idx >> 7, rem = idx & 127;
        int ii = rem >> 3, d = rem & 7;
        float va = x[((size_t)(b0 + 2*b2    ) * NI + i0 + ii) * 8 + d];
        float vb = x[((size_t)(b0 + 2*b2 + 1) * NI + i0 + ii) * 8 + d];
        sxp[b2][ii][d] = pk(va, vb);
    }
    __syncthreads();

    const float4* wp = reinterpret_cast<const float4*>(W)
                     + ((size_t)((t >> 4) * NI + i0) * 16 + (t & 15)) * 2;

    uint64_t s0[8];
#pragma unroll
    for (int k = 0; k < 8; ++k) s0[k] = 0ull;

    float4 wa = wp[0], wb = wp[1];
    for (int i = 0; i < IC; ++i) {
        float4 na, nb;
        if (i + 1 < IC) { na = wp[32]; nb = wp[33]; }
        wp += 32;

        uint64_t ws[8];
        ws[0] = pk(wa.x, wa.x); ws[1] = pk(wa.y, wa.y);
        ws[2] = pk(wa.z, wa.z); ws[3] = pk(wa.w, wa.w);
        ws[4] = pk(wb.x, wb.x); ws[5] = pk(wb.y, wb.y);
        ws[6] = pk(wb.z, wb.z); ws[7] = pk(wb.w, wb.w);

#pragma unroll
        for (int b2 = 0; b2 < 8; ++b2) {
            const ulonglong2* xp2 = reinterpret_cast<const ulonglong2*>(&sxp[b2][i][0]);
            ulonglong2 q0 = xp2[0], q1 = xp2[1];   // LDS.128 x2
            ulonglong2 q2 = xp2[2], q3 = xp2[3];
            uint64_t acc = mul2(ws[0], q0.x);
            fma2(acc, ws[1], q0.y);
            fma2(acc, ws[2], q1.x);
            fma2(acc, ws[3], q1.y);
            fma2(acc, ws[4], q2.x);
            fma2(acc, ws[5], q2.y);
            fma2(acc, ws[6], q3.x);
            fma2(acc, ws[7], q3.y);
            add2(s0[b2], acc);
            float lo, hi; unpk(acc, lo, hi);
            size_t base = ((size_t)(b0 + 2*b2) * NI + i0 + i) * 256 + t;
            g_hat[base]                    = __float2half_rn(lo);
            g_hat[base + (size_t)NI * 256] = __float2half_rn(hi);
        }
        wa = na; wb = nb;
    }
#pragma unroll
    for (int b2 = 0; b2 < 8; ++b2) {
        float lo, hi; unpk(s0[b2], lo, hi);
        g_s0p[((size_t)blockIdx.x * NB + b0 + 2*b2    ) * 256 + t] = lo;
        g_s0p[((size_t)blockIdx.x * NB + b0 + 2*b2 + 1) * 256 + t] = hi;
    }
}

// squash along e via warp butterfly over low 4 lane bits (t = n*16+e)
__device__ __forceinline__ float squash_val(float sv) {
    float sq = sv * sv;
    sq += __shfl_xor_sync(0xffffffffu, sq, 1);
    sq += __shfl_xor_sync(0xffffffffu, sq, 2);
    sq += __shfl_xor_sync(0xffffffffu, sq, 4);
    sq += __shfl_xor_sync(0xffffffffu, sq, 8);
    float scale = sq / ((1.f + sq) * sqrtf(sq));
    return sv * scale;
}

// One i: fp16 hat fragment -> logit dot (packed), softmax over n (4 shfl),
// packed-fma accumulate into sacc.
__device__ __forceinline__ void step_i(uint4 A0, uint4 A1,
                                       const uint64_t vecp[8], uint64_t sacc[8]) {
    uint64_t fp[8];
    const __half2* ha = reinterpret_cast<const __half2*>(&A0);
#pragma unroll
    for (int j = 0; j < 4; ++j) { float2 v = __half22float2(ha[j]); fp[j] = pk(v.x, v.y); }
    const __half2* hb = reinterpret_cast<const __half2*>(&A1);
#pragma unroll
    for (int j = 0; j < 4; ++j) { float2 v = __half22float2(hb[j]); fp[4+j] = pk(v.x, v.y); }

    uint64_t dacc = mul2(vecp[0], fp[0]);
#pragma unroll
    for (int j = 1; j < 8; ++j) fma2(dacc, vecp[j], fp[j]);
    float dlo, dhi; unpk(dacc, dlo, dhi);
    float E = __expf(dlo + dhi);
    float den = E;
    den += __shfl_xor_sync(0xffffffffu, den, 1);
    den += __shfl_xor_sync(0xffffffffu, den, 2);
    den += __shfl_xor_sync(0xffffffffu, den, 4);
    den += __shfl_xor_sync(0xffffffffu, den, 8);
    float c = __fdividef(E, den);
    uint64_t cp = pk(c, c);
#pragma unroll
    for (int j = 0; j < 8; ++j) fma2(sacc[j], cp, fp[j]);
}

// One full sweep over all NI i's for this CTA's batch. Lane: n = lane&15,
// islot = lane>>4; slot = warp*2+islot strides i by SLOTS. 2-step unroll.
__device__ __forceinline__ void sweep(const uint4* p, const uint64_t vecp[8],
                                      int n, int slot, float sRed[SLOTS][256]) {
    uint64_t sacc[8];
#pragma unroll
    for (int j = 0; j < 8; ++j) sacc[j] = 0ull;

    const int S = SLOTS * 32;
    uint4 A0 = p[0], A1 = p[1], B0 = p[S], B1 = p[S + 1];
#pragma unroll 2
    for (int s = 0; s < STEPS; s += 2) {
        uint4 C0, C1, D0, D1;
        if (s + 2 < STEPS) {
            C0 = p[2*S]; C1 = p[2*S + 1];
            D0 = p[3*S]; D1 = p[3*S + 1];
        }
        p += 2 * S;
        step_i(A0, A1, vecp, sacc);
        step_i(B0, B1, vecp, sacc);
        A0 = C0; A1 = C1; B0 = D0; B1 = D1;
    }
#pragma unroll
    for (int j = 0; j < 8; ++j) {
        float lo, hi; unpk(sacc[j], lo, hi);
        sRed[slot][n * 16 + 2*j]     = lo;
        sRed[slot][n * 16 + 2*j + 1] = hi;
    }
}

// ---------------------------------------------------------------------------
// k_route: ALL routing in one kernel, one CTA per batch (no cross-CTA deps).
// grid 128, 768 threads (24 warps). head(out0) -> pass1 -> out1 -> pass2 ->
// final squash -> out. hat is L2-resident (written by k_hat just before).
// ---------------------------------------------------------------------------
__global__ void __launch_bounds__(768) k_route(const float* __restrict__ Bias,
                                               float* __restrict__ out) {
    __shared__ float sVec[256];
    __shared__ float sOut0[256];
    __shared__ float sRed[SLOTS][256];   // 48KB

    const int b = blockIdx.x, t = threadIdx.x;
    const int warp = t >> 5, lane = t & 31;
    const int n = lane & 15, islot = lane >> 4;
    const int slot = warp * 2 + islot;

    // ---- head: out0 = squash(sum_i hat /16 + Bias) ----
    if (t < 256) {
        float sv = 0.f;
        for (int c = 0; c < ICHUNKS; ++c)
            sv += g_s0p[((size_t)c * NB + b) * 256 + t];
        sv = sv * (1.f / 16.f) + Bias[t];
        float o = squash_val(sv);
        sOut0[t] = o; sVec[t] = o;
    }
    __syncthreads();

    const uint4* p0 = reinterpret_cast<const uint4*>(g_hat)
                    + ((size_t)b * NI + slot) * 32 + n * 2;

    uint64_t vecp[8];
#pragma unroll
    for (int j = 0; j < 8; ++j)
        vecp[j] = pk(sVec[n * 16 + 2*j], sVec[n * 16 + 2*j + 1]);

    // ---- pass 1: b1 = out0 . hat ----
    sweep(p0, vecp, n, slot, sRed);
    __syncthreads();
    if (t < 256) {
        float sv = 0.f;
#pragma unroll
        for (int w = 0; w < SLOTS; ++w) sv += sRed[w][t];
        sv += Bias[t];
        sVec[t] = sOut0[t] + squash_val(sv);   // telescoped vec = out0 + out1
    }
    __syncthreads();

#pragma unroll
    for (int j = 0; j < 8; ++j)
        vecp[j] = pk(sVec[n * 16 + 2*j], sVec[n * 16 + 2*j + 1]);

    // ---- pass 2: b2 = (out0+out1) . hat, final squash ----
    sweep(p0, vecp, n, slot, sRed);
    __syncthreads();
    if (t < 256) {
        float sv = 0.f;
#pragma unroll
        for (int w = 0; w < SLOTS; ++w) sv += sRed[w][t];
        sv += Bias[t];
        out[b * 256 + t] = squash_val(sv);
    }
}

extern "C" void kernel_launch(void* const* d_in, const int* in_sizes, int n_in,
                              void* d_out, int out_size) {
    const float* x    = (const float*)d_in[0];   // [128,1152,8]
    const float* W    = (const float*)d_in[1];   // [16,1152,16,8]
    const float* Bias = (const float*)d_in[2];   // [16,16]
    float* out = (float*)d_out;                  // [128,16,16]

    k_hat<<<dim3(ICHUNKS, NB / 16), 256>>>(x, W);   // 576 CTAs
    k_route<<<NB, 768>>>(Bias, out);                // 128 CTAs, 1 per batch
}